// round 11
// baseline (speedup 1.0000x reference)
#include <cuda_runtime.h>
#include <math.h>
#include <stdint.h>

// ---------------------------------------------------------------------------
// Weighted Kabsch, fused, 4-deep TMA pipeline with full/empty mbarriers.
// Per CTA (one batch): TILE=256-point buffers x4 (28 KB static smem -> 8
// CTAs/SM). Thread 0 stages via cp.async.bulk; consumers wait on full
// barriers and arrive (1/warp) on empty barriers — no __syncthreads in the
// hot loop. Block-reduce 16 sufficient statistics; thread 0 runs the fp32
// 3x3 SVD + rigid-transform epilogue.
// ---------------------------------------------------------------------------

#define THREADS 128
#define TILE 256                 // points per tile (2 per thread)
#define NBUF 4

struct __align__(16) Smem {
    float src[NBUF][TILE * 3];   // 12 KB
    float tgt[NBUF][TILE * 3];   // 12 KB
    float wgt[NBUF][TILE];       //  4 KB
    float red[THREADS / 32][16];
    unsigned long long full[NBUF];
    unsigned long long empty[NBUF];
};

__device__ __forceinline__ void mbar_init(uint32_t a, uint32_t cnt) {
    asm volatile("mbarrier.init.shared.b64 [%0], %1;" :: "r"(a), "r"(cnt) : "memory");
}
__device__ __forceinline__ void mbar_expect_tx(uint32_t a, uint32_t bytes) {
    asm volatile("mbarrier.arrive.expect_tx.shared.b64 _, [%0], %1;"
                 :: "r"(a), "r"(bytes) : "memory");
}
__device__ __forceinline__ void mbar_arrive(uint32_t a) {
    asm volatile("mbarrier.arrive.shared.b64 _, [%0];" :: "r"(a) : "memory");
}
__device__ __forceinline__ void bulk_g2s(uint32_t sdst, const void* gsrc,
                                         uint32_t bytes, uint32_t mbar) {
    asm volatile(
        "cp.async.bulk.shared::cta.global.mbarrier::complete_tx::bytes [%0], [%1], %2, [%3];"
        :: "r"(sdst), "l"(gsrc), "r"(bytes), "r"(mbar) : "memory");
}
__device__ __forceinline__ void mbar_wait(uint32_t a, uint32_t parity) {
    uint32_t done;
    asm volatile(
        "{\n\t.reg .pred p;\n\t"
        "mbarrier.try_wait.parity.acquire.cta.shared::cta.b64 p, [%1], %2;\n\t"
        "selp.b32 %0, 1, 0, p;\n\t}"
        : "=r"(done) : "r"(a), "r"(parity) : "memory");
    if (!done) {
        asm volatile(
            "{\n\t.reg .pred P1;\n\t"
            "WL_%=:\n\t"
            "mbarrier.try_wait.parity.acquire.cta.shared::cta.b64 P1, [%0], %1, 0x989680;\n\t"
            "@P1 bra.uni WD_%=;\n\t"
            "bra.uni WL_%=;\n\t"
            "WD_%=:\n\t}"
            :: "r"(a), "r"(parity) : "memory");
    }
}

__device__ __forceinline__ float det3f(const float m[3][3]) {
    return m[0][0] * (m[1][1] * m[2][2] - m[1][2] * m[2][1])
         - m[0][1] * (m[1][0] * m[2][2] - m[1][2] * m[2][0])
         + m[0][2] * (m[1][0] * m[2][1] - m[1][1] * m[2][0]);
}

__global__ void __launch_bounds__(THREADS)
kabsch_kernel(const float* __restrict__ src,
              const float* __restrict__ tgt,
              const float* __restrict__ wts,
              float* __restrict__ out,
              int N, int B)
{
    __shared__ Smem sm;

    const int b = blockIdx.x;
    const int tid = threadIdx.x;
    const int lane = tid & 31;
    const char* gS = (const char*)(src + (size_t)b * N * 3);
    const char* gT = (const char*)(tgt + (size_t)b * N * 3);
    const char* gW = (const char*)(wts + (size_t)b * N);

    const int ntiles = (N + TILE - 1) / TILE;

    uint32_t fb[NBUF], eb[NBUF], sS[NBUF], sT[NBUF], sW[NBUF];
#pragma unroll
    for (int i = 0; i < NBUF; i++) {
        fb[i] = (uint32_t)__cvta_generic_to_shared(&sm.full[i]);
        eb[i] = (uint32_t)__cvta_generic_to_shared(&sm.empty[i]);
        sS[i] = (uint32_t)__cvta_generic_to_shared(&sm.src[i][0]);
        sT[i] = (uint32_t)__cvta_generic_to_shared(&sm.tgt[i][0]);
        sW[i] = (uint32_t)__cvta_generic_to_shared(&sm.wgt[i][0]);
    }

    if (tid == 0) {
#pragma unroll
        for (int i = 0; i < NBUF; i++) {
            mbar_init(fb[i], 1);                 // tx-based completion
            mbar_init(eb[i], THREADS / 32);      // one arrive per warp
        }
    }
    __syncthreads();

    auto stage = [&](int t) {
        const int bf = t & (NBUF - 1);
        const int npts = min(TILE, N - t * TILE);
        const uint32_t cbytes = (uint32_t)npts * 12u;
        const uint32_t wbytes = (uint32_t)npts * 4u;
        mbar_expect_tx(fb[bf], 2u * cbytes + wbytes);
        bulk_g2s(sS[bf], gS + (size_t)t * TILE * 12, cbytes, fb[bf]);
        bulk_g2s(sT[bf], gT + (size_t)t * TILE * 12, cbytes, fb[bf]);
        bulk_g2s(sW[bf], gW + (size_t)t * TILE * 4,  wbytes, fb[bf]);
    };

    // producer prologue: fill the pipeline (empty-wait with initial parity 1
    // passes immediately on fresh barriers)
    int stage_t = 0;
    if (tid == 0) {
        const int npre = min(ntiles, NBUF);
        for (; stage_t < npre; stage_t++) stage(stage_t);
    }

    float acc[16];
#pragma unroll
    for (int i = 0; i < 16; i++) acc[i] = 0.f;

    for (int t = 0; t < ntiles; t++) {
        const int bf = t & (NBUF - 1);
        mbar_wait(fb[bf], (uint32_t)(t / NBUF) & 1u);

        const int npts = min(TILE, N - t * TILE);
        const float2* S2 = (const float2*)sm.src[bf];
        const float2* T2 = (const float2*)sm.tgt[bf];
        const float2* W2 = (const float2*)sm.wgt[bf];

        // thread handles points 2*tid, 2*tid+1 (LDS.64, conflict-free)
        if (tid * 2 < npts) {
            const float2 w2 = W2[tid];
            const float2 sa = S2[tid * 3 + 0];
            const float2 sbv = S2[tid * 3 + 1];
            const float2 scv = S2[tid * 3 + 2];
            const float2 ta = T2[tid * 3 + 0];
            const float2 tbv = T2[tid * 3 + 1];
            const float2 tcv = T2[tid * 3 + 2];

            const float sx[2][3] = {{sa.x, sa.y, sbv.x}, {sbv.y, scv.x, scv.y}};
            const float tx[2][3] = {{ta.x, ta.y, tbv.x}, {tbv.y, tcv.x, tcv.y}};
            const float wa[2] = {w2.x, w2.y};
            const int np = (tid * 2 + 1 < npts) ? 2 : 1;

#pragma unroll
            for (int p = 0; p < 2; p++) {
                if (p >= np) break;
                const float w = wa[p];
                const float s0 = sx[p][0], s1 = sx[p][1], s2 = sx[p][2];
                const float wt0 = w * tx[p][0];
                const float wt1 = w * tx[p][1];
                const float wt2 = w * tx[p][2];
                acc[0] += w;
                acc[1] += w * s0;  acc[2] += w * s1;  acc[3] += w * s2;
                acc[4] += wt0;     acc[5] += wt1;     acc[6] += wt2;
                acc[7]  += wt0 * s0;  acc[8]  += wt0 * s1;  acc[9]  += wt0 * s2;
                acc[10] += wt1 * s0;  acc[11] += wt1 * s1;  acc[12] += wt1 * s2;
                acc[13] += wt2 * s0;  acc[14] += wt2 * s1;  acc[15] += wt2 * s2;
            }
        }

        // mark this warp done with buffer bf
        __syncwarp();
        if (lane == 0) mbar_arrive(eb[bf]);

        // producer: re-stage into freed buffer (blocks only thread 0)
        if (tid == 0 && stage_t < ntiles) {
            const int sbf = stage_t & (NBUF - 1);
            mbar_wait(eb[sbf], 1u ^ ((uint32_t)(stage_t / NBUF) & 1u));
            stage(stage_t);
            stage_t++;
        }
    }

    // warp reduce
#pragma unroll
    for (int i = 0; i < 16; i++) {
#pragma unroll
        for (int o = 16; o > 0; o >>= 1)
            acc[i] += __shfl_down_sync(0xffffffffu, acc[i], o);
    }

    const int warp = tid >> 5;
    if (lane == 0) {
#pragma unroll
        for (int i = 0; i < 16; i++) sm.red[warp][i] = acc[i];
    }
    __syncthreads();

    if (tid != 0) return;

    // ---- thread 0: finalize stats, fast fp32 3x3 SVD + epilogue ----
    float s[16];
#pragma unroll
    for (int i = 0; i < 16; i++) {
        float v = sm.red[0][i];
#pragma unroll
        for (int w = 1; w < THREADS / 32; w++) v += sm.red[w][i];
        s[i] = v;
    }

    const float Sw = s[0];
    const float Sx[3] = {s[1], s[2], s[3]};
    const float Tx[3] = {s[4], s[5], s[6]};
    const float M[3][3] = {{s[7], s[8], s[9]},
                           {s[10], s[11], s[12]},
                           {s[13], s[14], s[15]}};

    const float w = Sw + 1e-4f;
    const float winv = __fdividef(1.0f, w);
    float sc[3], tc[3];
#pragma unroll
    for (int i = 0; i < 3; i++) { sc[i] = Sx[i] * winv; tc[i] = Tx[i] * winv; }

    float A[3][3];
#pragma unroll
    for (int i = 0; i < 3; i++)
#pragma unroll
        for (int j = 0; j < 3; j++)
            A[i][j] = (M[i][j] - tc[i] * Sx[j] - Tx[i] * sc[j] + Sw * tc[i] * sc[j]) * winv;

    float Bm[3][3];
#pragma unroll
    for (int i = 0; i < 3; i++)
#pragma unroll
        for (int j = 0; j < 3; j++)
            Bm[i][j] = A[0][i] * A[0][j] + A[1][i] * A[1][j] + A[2][i] * A[2][j];

    float V[3][3] = {{1, 0, 0}, {0, 1, 0}, {0, 0, 1}};

    // cyclic Jacobi, 5 sweeps, fast divides, convergence skip
#pragma unroll 1
    for (int sweep = 0; sweep < 5; sweep++) {
#pragma unroll
        for (int pair = 0; pair < 3; pair++) {
            const int p = (pair == 2) ? 1 : 0;
            const int q = (pair == 0) ? 1 : 2;
            const float apq = Bm[p][q];
            const float app = Bm[p][p], aqq = Bm[q][q];
            if (apq * apq <= 1e-22f * app * aqq + 1e-38f) continue;
            const float tau = __fdividef(aqq - app, 2.0f * apq);
            const float t = __fdividef((tau >= 0.0f) ? 1.0f : -1.0f,
                                       fabsf(tau) + sqrtf(1.0f + tau * tau));
            const float c = rsqrtf(1.0f + t * t);
            const float sn = t * c;
#pragma unroll
            for (int k = 0; k < 3; k++) {
                const float bkp = Bm[k][p], bkq = Bm[k][q];
                Bm[k][p] = c * bkp - sn * bkq;
                Bm[k][q] = sn * bkp + c * bkq;
            }
#pragma unroll
            for (int k = 0; k < 3; k++) {
                const float bpk = Bm[p][k], bqk = Bm[q][k];
                Bm[p][k] = c * bpk - sn * bqk;
                Bm[q][k] = sn * bpk + c * bqk;
            }
#pragma unroll
            for (int k = 0; k < 3; k++) {
                const float vkp = V[k][p], vkq = V[k][q];
                V[k][p] = c * vkp - sn * vkq;
                V[k][q] = sn * vkp + c * vkq;
            }
        }
    }

    float lam[3] = {Bm[0][0], Bm[1][1], Bm[2][2]};
#pragma unroll
    for (int i = 0; i < 2; i++)
#pragma unroll
        for (int j = 0; j < 2 - i; j++)
            if (lam[j] < lam[j + 1]) {
                float tl = lam[j]; lam[j] = lam[j + 1]; lam[j + 1] = tl;
#pragma unroll
                for (int k = 0; k < 3; k++) {
                    float tv = V[k][j]; V[k][j] = V[k][j + 1]; V[k][j + 1] = tv;
                }
            }

    float U[3][3];
    float norms[3];
#pragma unroll
    for (int k = 0; k < 3; k++) {
        float uv[3];
#pragma unroll
        for (int i = 0; i < 3; i++)
            uv[i] = A[i][0] * V[0][k] + A[i][1] * V[1][k] + A[i][2] * V[2][k];
        const float nsq = uv[0] * uv[0] + uv[1] * uv[1] + uv[2] * uv[2];
        norms[k] = sqrtf(nsq);
        const float inv = (nsq > 1e-36f) ? rsqrtf(nsq) : 0.0f;
#pragma unroll
        for (int i = 0; i < 3; i++) U[i][k] = uv[i] * inv;
    }
    if (norms[2] < 1e-7f * (norms[0] + 1e-30f)) {
        U[0][2] = U[1][0] * U[2][1] - U[2][0] * U[1][1];
        U[1][2] = U[2][0] * U[0][1] - U[0][0] * U[2][1];
        U[2][2] = U[0][0] * U[1][1] - U[1][0] * U[0][1];
    }

    const float d = det3f(U) * det3f(V);

    float R[3][3];
#pragma unroll
    for (int i = 0; i < 3; i++)
#pragma unroll
        for (int j = 0; j < 3; j++)
            R[i][j] = U[i][0] * V[j][0] + U[i][1] * V[j][1] + d * U[i][2] * V[j][2];

    float t1[3], t[3];
#pragma unroll
    for (int i = 0; i < 3; i++)
        t1[i] = sc[i] - (R[0][i] * tc[0] + R[1][i] * tc[1] + R[2][i] * tc[2]);
#pragma unroll
    for (int i = 0; i < 3; i++)
        t[i] = -(R[i][0] * t1[0] + R[i][1] * t1[1] + R[i][2] * t1[2]);

    float* Rout = out + (size_t)b * 9;
    float* Tout = out + (size_t)B * 9 + (size_t)b * 3;
#pragma unroll
    for (int i = 0; i < 3; i++)
#pragma unroll
        for (int j = 0; j < 3; j++)
            Rout[i * 3 + j] = R[i][j];
#pragma unroll
    for (int i = 0; i < 3; i++) Tout[i] = t[i];
}

// ---------------------------------------------------------------------------

extern "C" void kernel_launch(void* const* d_in, const int* in_sizes, int n_in,
                              void* d_out, int out_size)
{
    const float* src = (const float*)d_in[0];
    const float* tgt = (const float*)d_in[1];
    const float* wts = (const float*)d_in[2];
    float* out = (float*)d_out;

    const int B = out_size / 12;            // 9 (R) + 3 (t) per batch
    const int N = in_sizes[2] / B;          // weights are (B,1,N)

    kabsch_kernel<<<B, THREADS>>>(src, tgt, wts, out, N, B);
}

// round 12
// speedup vs baseline: 1.0672x; 1.0672x over previous
#include <cuda_runtime.h>
#include <math.h>
#include <stdint.h>

// ---------------------------------------------------------------------------
// Weighted Kabsch, fused, TMA-bulk staged (R9 structure, 256 threads).
// Per CTA (one batch): double-buffered cp.async.bulk tiles (3 instructions per
// tile from thread 0, mbarrier completion), 256 consumer threads read float2
// (2 points/thread), accumulate 16 sufficient statistics, block-reduce;
// thread 0 runs the fp32 3x3 SVD + rigid-transform epilogue.
// ---------------------------------------------------------------------------

#define THREADS 256
#define TILE 512                 // points per tile (2 per thread)

struct __align__(16) Smem {
    float src[2][TILE * 3];      // 12 KB
    float tgt[2][TILE * 3];      // 12 KB
    float wgt[2][TILE];          //  4 KB
    float red[THREADS / 32][16];
    unsigned long long mbar[2];
};

__device__ __forceinline__ void mbar_init(uint32_t a, uint32_t cnt) {
    asm volatile("mbarrier.init.shared.b64 [%0], %1;" :: "r"(a), "r"(cnt) : "memory");
}
__device__ __forceinline__ void mbar_expect_tx(uint32_t a, uint32_t bytes) {
    asm volatile("mbarrier.arrive.expect_tx.shared.b64 _, [%0], %1;"
                 :: "r"(a), "r"(bytes) : "memory");
}
__device__ __forceinline__ void bulk_g2s(uint32_t sdst, const void* gsrc,
                                         uint32_t bytes, uint32_t mbar) {
    asm volatile(
        "cp.async.bulk.shared::cta.global.mbarrier::complete_tx::bytes [%0], [%1], %2, [%3];"
        :: "r"(sdst), "l"(gsrc), "r"(bytes), "r"(mbar) : "memory");
}
__device__ __forceinline__ void mbar_wait(uint32_t a, uint32_t parity) {
    uint32_t done;
    asm volatile(
        "{\n\t.reg .pred p;\n\t"
        "mbarrier.try_wait.parity.acquire.cta.shared::cta.b64 p, [%1], %2;\n\t"
        "selp.b32 %0, 1, 0, p;\n\t}"
        : "=r"(done) : "r"(a), "r"(parity) : "memory");
    if (!done) {
        asm volatile(
            "{\n\t.reg .pred P1;\n\t"
            "WL_%=:\n\t"
            "mbarrier.try_wait.parity.acquire.cta.shared::cta.b64 P1, [%0], %1, 0x989680;\n\t"
            "@P1 bra.uni WD_%=;\n\t"
            "bra.uni WL_%=;\n\t"
            "WD_%=:\n\t}"
            :: "r"(a), "r"(parity) : "memory");
    }
}

__device__ __forceinline__ float det3f(const float m[3][3]) {
    return m[0][0] * (m[1][1] * m[2][2] - m[1][2] * m[2][1])
         - m[0][1] * (m[1][0] * m[2][2] - m[1][2] * m[2][0])
         + m[0][2] * (m[1][0] * m[2][1] - m[1][1] * m[2][0]);
}

__global__ void __launch_bounds__(THREADS)
kabsch_kernel(const float* __restrict__ src,
              const float* __restrict__ tgt,
              const float* __restrict__ wts,
              float* __restrict__ out,
              int N, int B)
{
    __shared__ Smem sm;

    const int b = blockIdx.x;
    const int tid = threadIdx.x;
    const char* gS = (const char*)(src + (size_t)b * N * 3);
    const char* gT = (const char*)(tgt + (size_t)b * N * 3);
    const char* gW = (const char*)(wts + (size_t)b * N);

    const int ntiles = (N + TILE - 1) / TILE;

    const uint32_t mb[2] = {
        (uint32_t)__cvta_generic_to_shared(&sm.mbar[0]),
        (uint32_t)__cvta_generic_to_shared(&sm.mbar[1])
    };
    const uint32_t sS[2] = { (uint32_t)__cvta_generic_to_shared(&sm.src[0][0]),
                             (uint32_t)__cvta_generic_to_shared(&sm.src[1][0]) };
    const uint32_t sT[2] = { (uint32_t)__cvta_generic_to_shared(&sm.tgt[0][0]),
                             (uint32_t)__cvta_generic_to_shared(&sm.tgt[1][0]) };
    const uint32_t sW[2] = { (uint32_t)__cvta_generic_to_shared(&sm.wgt[0][0]),
                             (uint32_t)__cvta_generic_to_shared(&sm.wgt[1][0]) };

    if (tid == 0) {
        mbar_init(mb[0], 1);
        mbar_init(mb[1], 1);
    }
    __syncthreads();

    auto stage = [&](int t, int bf) {
        const int npts = min(TILE, N - t * TILE);
        const uint32_t cbytes = (uint32_t)npts * 12u;
        const uint32_t wbytes = (uint32_t)npts * 4u;
        mbar_expect_tx(mb[bf], 2u * cbytes + wbytes);
        bulk_g2s(sS[bf], gS + (size_t)t * TILE * 12, cbytes, mb[bf]);
        bulk_g2s(sT[bf], gT + (size_t)t * TILE * 12, cbytes, mb[bf]);
        bulk_g2s(sW[bf], gW + (size_t)t * TILE * 4,  wbytes, mb[bf]);
    };

    float acc[16];
#pragma unroll
    for (int i = 0; i < 16; i++) acc[i] = 0.f;

    if (tid == 0) stage(0, 0);

    for (int t = 0; t < ntiles; t++) {
        const int bf = t & 1;
        if (tid == 0 && t + 1 < ntiles) stage(t + 1, bf ^ 1);

        mbar_wait(mb[bf], (uint32_t)(t >> 1) & 1u);

        const int npts = min(TILE, N - t * TILE);
        const float2* S2 = (const float2*)sm.src[bf];
        const float2* T2 = (const float2*)sm.tgt[bf];
        const float2* W2 = (const float2*)sm.wgt[bf];

        // thread handles points 2*tid, 2*tid+1 (LDS.64)
        if (tid * 2 < npts) {
            const float2 w2 = W2[tid];
            const float2 sa = S2[tid * 3 + 0];
            const float2 sb = S2[tid * 3 + 1];
            const float2 sc2 = S2[tid * 3 + 2];
            const float2 ta = T2[tid * 3 + 0];
            const float2 tb = T2[tid * 3 + 1];
            const float2 tc2 = T2[tid * 3 + 2];

            const float sx[2][3] = {{sa.x, sa.y, sb.x}, {sb.y, sc2.x, sc2.y}};
            const float tx[2][3] = {{ta.x, ta.y, tb.x}, {tb.y, tc2.x, tc2.y}};
            const float wa[2] = {w2.x, w2.y};
            const int np = (tid * 2 + 1 < npts) ? 2 : 1;

#pragma unroll
            for (int p = 0; p < 2; p++) {
                if (p >= np) break;
                const float w = wa[p];
                const float s0 = sx[p][0], s1 = sx[p][1], s2 = sx[p][2];
                const float wt0 = w * tx[p][0];
                const float wt1 = w * tx[p][1];
                const float wt2 = w * tx[p][2];
                acc[0] += w;
                acc[1] += w * s0;  acc[2] += w * s1;  acc[3] += w * s2;
                acc[4] += wt0;     acc[5] += wt1;     acc[6] += wt2;
                acc[7]  += wt0 * s0;  acc[8]  += wt0 * s1;  acc[9]  += wt0 * s2;
                acc[10] += wt1 * s0;  acc[11] += wt1 * s1;  acc[12] += wt1 * s2;
                acc[13] += wt2 * s0;  acc[14] += wt2 * s1;  acc[15] += wt2 * s2;
            }
        }
        __syncthreads();
    }

    // warp reduce
#pragma unroll
    for (int i = 0; i < 16; i++) {
#pragma unroll
        for (int o = 16; o > 0; o >>= 1)
            acc[i] += __shfl_down_sync(0xffffffffu, acc[i], o);
    }

    const int warp = tid >> 5;
    const int lane = tid & 31;
    if (lane == 0) {
#pragma unroll
        for (int i = 0; i < 16; i++) sm.red[warp][i] = acc[i];
    }
    __syncthreads();

    if (tid != 0) return;

    // ---- thread 0: finalize stats, fast fp32 3x3 SVD + epilogue ----
    float s[16];
#pragma unroll
    for (int i = 0; i < 16; i++) {
        float v = sm.red[0][i];
#pragma unroll
        for (int w = 1; w < THREADS / 32; w++) v += sm.red[w][i];
        s[i] = v;
    }

    const float Sw = s[0];
    const float Sx[3] = {s[1], s[2], s[3]};
    const float Tx[3] = {s[4], s[5], s[6]};
    const float M[3][3] = {{s[7], s[8], s[9]},
                           {s[10], s[11], s[12]},
                           {s[13], s[14], s[15]}};

    const float w = Sw + 1e-4f;
    const float winv = __fdividef(1.0f, w);
    float sc[3], tc[3];
#pragma unroll
    for (int i = 0; i < 3; i++) { sc[i] = Sx[i] * winv; tc[i] = Tx[i] * winv; }

    float A[3][3];
#pragma unroll
    for (int i = 0; i < 3; i++)
#pragma unroll
        for (int j = 0; j < 3; j++)
            A[i][j] = (M[i][j] - tc[i] * Sx[j] - Tx[i] * sc[j] + Sw * tc[i] * sc[j]) * winv;

    float Bm[3][3];
#pragma unroll
    for (int i = 0; i < 3; i++)
#pragma unroll
        for (int j = 0; j < 3; j++)
            Bm[i][j] = A[0][i] * A[0][j] + A[1][i] * A[1][j] + A[2][i] * A[2][j];

    float V[3][3] = {{1, 0, 0}, {0, 1, 0}, {0, 0, 1}};

    // cyclic Jacobi, 5 sweeps, fast divides, convergence skip
#pragma unroll 1
    for (int sweep = 0; sweep < 5; sweep++) {
#pragma unroll
        for (int pair = 0; pair < 3; pair++) {
            const int p = (pair == 2) ? 1 : 0;
            const int q = (pair == 0) ? 1 : 2;
            const float apq = Bm[p][q];
            const float app = Bm[p][p], aqq = Bm[q][q];
            if (apq * apq <= 1e-22f * app * aqq + 1e-38f) continue;
            const float tau = __fdividef(aqq - app, 2.0f * apq);
            const float t = __fdividef((tau >= 0.0f) ? 1.0f : -1.0f,
                                       fabsf(tau) + sqrtf(1.0f + tau * tau));
            const float c = rsqrtf(1.0f + t * t);
            const float sn = t * c;
#pragma unroll
            for (int k = 0; k < 3; k++) {
                const float bkp = Bm[k][p], bkq = Bm[k][q];
                Bm[k][p] = c * bkp - sn * bkq;
                Bm[k][q] = sn * bkp + c * bkq;
            }
#pragma unroll
            for (int k = 0; k < 3; k++) {
                const float bpk = Bm[p][k], bqk = Bm[q][k];
                Bm[p][k] = c * bpk - sn * bqk;
                Bm[q][k] = sn * bpk + c * bqk;
            }
#pragma unroll
            for (int k = 0; k < 3; k++) {
                const float vkp = V[k][p], vkq = V[k][q];
                V[k][p] = c * vkp - sn * vkq;
                V[k][q] = sn * vkp + c * vkq;
            }
        }
    }

    float lam[3] = {Bm[0][0], Bm[1][1], Bm[2][2]};
#pragma unroll
    for (int i = 0; i < 2; i++)
#pragma unroll
        for (int j = 0; j < 2 - i; j++)
            if (lam[j] < lam[j + 1]) {
                float tl = lam[j]; lam[j] = lam[j + 1]; lam[j + 1] = tl;
#pragma unroll
                for (int k = 0; k < 3; k++) {
                    float tv = V[k][j]; V[k][j] = V[k][j + 1]; V[k][j + 1] = tv;
                }
            }

    float U[3][3];
    float norms[3];
#pragma unroll
    for (int k = 0; k < 3; k++) {
        float uv[3];
#pragma unroll
        for (int i = 0; i < 3; i++)
            uv[i] = A[i][0] * V[0][k] + A[i][1] * V[1][k] + A[i][2] * V[2][k];
        const float nsq = uv[0] * uv[0] + uv[1] * uv[1] + uv[2] * uv[2];
        norms[k] = sqrtf(nsq);
        const float inv = (nsq > 1e-36f) ? rsqrtf(nsq) : 0.0f;
#pragma unroll
        for (int i = 0; i < 3; i++) U[i][k] = uv[i] * inv;
    }
    if (norms[2] < 1e-7f * (norms[0] + 1e-30f)) {
        U[0][2] = U[1][0] * U[2][1] - U[2][0] * U[1][1];
        U[1][2] = U[2][0] * U[0][1] - U[0][0] * U[2][1];
        U[2][2] = U[0][0] * U[1][1] - U[1][0] * U[0][1];
    }

    const float d = det3f(U) * det3f(V);

    float R[3][3];
#pragma unroll
    for (int i = 0; i < 3; i++)
#pragma unroll
        for (int j = 0; j < 3; j++)
            R[i][j] = U[i][0] * V[j][0] + U[i][1] * V[j][1] + d * U[i][2] * V[j][2];

    float t1[3], t[3];
#pragma unroll
    for (int i = 0; i < 3; i++)
        t1[i] = sc[i] - (R[0][i] * tc[0] + R[1][i] * tc[1] + R[2][i] * tc[2]);
#pragma unroll
    for (int i = 0; i < 3; i++)
        t[i] = -(R[i][0] * t1[0] + R[i][1] * t1[1] + R[i][2] * t1[2]);

    float* Rout = out + (size_t)b * 9;
    float* Tout = out + (size_t)B * 9 + (size_t)b * 3;
#pragma unroll
    for (int i = 0; i < 3; i++)
#pragma unroll
        for (int j = 0; j < 3; j++)
            Rout[i * 3 + j] = R[i][j];
#pragma unroll
    for (int i = 0; i < 3; i++) Tout[i] = t[i];
}

// ---------------------------------------------------------------------------

extern "C" void kernel_launch(void* const* d_in, const int* in_sizes, int n_in,
                              void* d_out, int out_size)
{
    const float* src = (const float*)d_in[0];
    const float* tgt = (const float*)d_in[1];
    const float* wts = (const float*)d_in[2];
    float* out = (float*)d_out;

    const int B = out_size / 12;            // 9 (R) + 3 (t) per batch
    const int N = in_sizes[2] / B;          // weights are (B,1,N)

    kabsch_kernel<<<B, THREADS>>>(src, tgt, wts, out, N, B);
}

// round 13
// speedup vs baseline: 1.0738x; 1.0061x over previous
#include <cuda_runtime.h>
#include <math.h>
#include <stdint.h>

// ---------------------------------------------------------------------------
// Weighted Kabsch, fused, 4-deep TMA pipeline, minimal machinery.
// TILE=256 points x NBUF=4 buffers = same 28 KB smem footprint as the best
// 2-deep variant (7-8 CTAs/SM) but with 3 tiles of TMA lookahead. One
// __syncthreads per tile; thread 0 stages; tx-count mbarriers signal arrival.
// Block-reduce 16 sufficient statistics; thread 0 runs the fp32 3x3 SVD +
// rigid-transform epilogue.
// ---------------------------------------------------------------------------

#define THREADS 128
#define TILE 256                 // points per tile (2 per thread)
#define NBUF 4

struct __align__(16) Smem {
    float src[NBUF][TILE * 3];   // 12 KB
    float tgt[NBUF][TILE * 3];   // 12 KB
    float wgt[NBUF][TILE];       //  4 KB
    float red[THREADS / 32][16];
    unsigned long long mbar[NBUF];
};

__device__ __forceinline__ void mbar_init(uint32_t a, uint32_t cnt) {
    asm volatile("mbarrier.init.shared.b64 [%0], %1;" :: "r"(a), "r"(cnt) : "memory");
}
__device__ __forceinline__ void mbar_expect_tx(uint32_t a, uint32_t bytes) {
    asm volatile("mbarrier.arrive.expect_tx.shared.b64 _, [%0], %1;"
                 :: "r"(a), "r"(bytes) : "memory");
}
__device__ __forceinline__ void bulk_g2s(uint32_t sdst, const void* gsrc,
                                         uint32_t bytes, uint32_t mbar) {
    asm volatile(
        "cp.async.bulk.shared::cta.global.mbarrier::complete_tx::bytes [%0], [%1], %2, [%3];"
        :: "r"(sdst), "l"(gsrc), "r"(bytes), "r"(mbar) : "memory");
}
__device__ __forceinline__ void mbar_wait(uint32_t a, uint32_t parity) {
    uint32_t done;
    asm volatile(
        "{\n\t.reg .pred p;\n\t"
        "mbarrier.try_wait.parity.acquire.cta.shared::cta.b64 p, [%1], %2;\n\t"
        "selp.b32 %0, 1, 0, p;\n\t}"
        : "=r"(done) : "r"(a), "r"(parity) : "memory");
    if (!done) {
        asm volatile(
            "{\n\t.reg .pred P1;\n\t"
            "WL_%=:\n\t"
            "mbarrier.try_wait.parity.acquire.cta.shared::cta.b64 P1, [%0], %1, 0x989680;\n\t"
            "@P1 bra.uni WD_%=;\n\t"
            "bra.uni WL_%=;\n\t"
            "WD_%=:\n\t}"
            :: "r"(a), "r"(parity) : "memory");
    }
}

__device__ __forceinline__ float det3f(const float m[3][3]) {
    return m[0][0] * (m[1][1] * m[2][2] - m[1][2] * m[2][1])
         - m[0][1] * (m[1][0] * m[2][2] - m[1][2] * m[2][0])
         + m[0][2] * (m[1][0] * m[2][1] - m[1][1] * m[2][0]);
}

__global__ void __launch_bounds__(THREADS)
kabsch_kernel(const float* __restrict__ src,
              const float* __restrict__ tgt,
              const float* __restrict__ wts,
              float* __restrict__ out,
              int N, int B)
{
    __shared__ Smem sm;

    const int b = blockIdx.x;
    const int tid = threadIdx.x;
    const char* gS = (const char*)(src + (size_t)b * N * 3);
    const char* gT = (const char*)(tgt + (size_t)b * N * 3);
    const char* gW = (const char*)(wts + (size_t)b * N);

    const int ntiles = (N + TILE - 1) / TILE;

    uint32_t mb[NBUF], sS[NBUF], sT[NBUF], sW[NBUF];
#pragma unroll
    for (int i = 0; i < NBUF; i++) {
        mb[i] = (uint32_t)__cvta_generic_to_shared(&sm.mbar[i]);
        sS[i] = (uint32_t)__cvta_generic_to_shared(&sm.src[i][0]);
        sT[i] = (uint32_t)__cvta_generic_to_shared(&sm.tgt[i][0]);
        sW[i] = (uint32_t)__cvta_generic_to_shared(&sm.wgt[i][0]);
    }

    if (tid == 0) {
#pragma unroll
        for (int i = 0; i < NBUF; i++) mbar_init(mb[i], 1);
    }
    __syncthreads();

    auto stage = [&](int t) {
        const int bf = t & (NBUF - 1);
        const int npts = min(TILE, N - t * TILE);
        const uint32_t cbytes = (uint32_t)npts * 12u;
        const uint32_t wbytes = (uint32_t)npts * 4u;
        mbar_expect_tx(mb[bf], 2u * cbytes + wbytes);
        bulk_g2s(sS[bf], gS + (size_t)t * TILE * 12, cbytes, mb[bf]);
        bulk_g2s(sT[bf], gT + (size_t)t * TILE * 12, cbytes, mb[bf]);
        bulk_g2s(sW[bf], gW + (size_t)t * TILE * 4,  wbytes, mb[bf]);
    };

    // prologue: 3-tile lookahead (buffer t+3 reused only after tile t-1 has
    // been consumed and barriered)
    if (tid == 0) {
        const int npre = min(ntiles, NBUF - 1);
        for (int t = 0; t < npre; t++) stage(t);
    }

    float acc[16];
#pragma unroll
    for (int i = 0; i < 16; i++) acc[i] = 0.f;

    for (int t = 0; t < ntiles; t++) {
        const int bf = t & (NBUF - 1);
        mbar_wait(mb[bf], (uint32_t)(t / NBUF) & 1u);

        const int npts = min(TILE, N - t * TILE);
        const float2* S2 = (const float2*)sm.src[bf];
        const float2* T2 = (const float2*)sm.tgt[bf];
        const float2* W2 = (const float2*)sm.wgt[bf];

        // thread handles points 2*tid, 2*tid+1 (LDS.64)
        if (tid * 2 < npts) {
            const float2 w2 = W2[tid];
            const float2 sa = S2[tid * 3 + 0];
            const float2 sb = S2[tid * 3 + 1];
            const float2 sc2 = S2[tid * 3 + 2];
            const float2 ta = T2[tid * 3 + 0];
            const float2 tb = T2[tid * 3 + 1];
            const float2 tc2 = T2[tid * 3 + 2];

            const float sx[2][3] = {{sa.x, sa.y, sb.x}, {sb.y, sc2.x, sc2.y}};
            const float tx[2][3] = {{ta.x, ta.y, tb.x}, {tb.y, tc2.x, tc2.y}};
            const float wa[2] = {w2.x, w2.y};
            const int np = (tid * 2 + 1 < npts) ? 2 : 1;

#pragma unroll
            for (int p = 0; p < 2; p++) {
                if (p >= np) break;
                const float w = wa[p];
                const float s0 = sx[p][0], s1 = sx[p][1], s2 = sx[p][2];
                const float wt0 = w * tx[p][0];
                const float wt1 = w * tx[p][1];
                const float wt2 = w * tx[p][2];
                acc[0] += w;
                acc[1] += w * s0;  acc[2] += w * s1;  acc[3] += w * s2;
                acc[4] += wt0;     acc[5] += wt1;     acc[6] += wt2;
                acc[7]  += wt0 * s0;  acc[8]  += wt0 * s1;  acc[9]  += wt0 * s2;
                acc[10] += wt1 * s0;  acc[11] += wt1 * s1;  acc[12] += wt1 * s2;
                acc[13] += wt2 * s0;  acc[14] += wt2 * s1;  acc[15] += wt2 * s2;
            }
        }
        __syncthreads();
        if (tid == 0 && t + NBUF - 1 < ntiles) stage(t + NBUF - 1);
    }

    // warp reduce
#pragma unroll
    for (int i = 0; i < 16; i++) {
#pragma unroll
        for (int o = 16; o > 0; o >>= 1)
            acc[i] += __shfl_down_sync(0xffffffffu, acc[i], o);
    }

    const int warp = tid >> 5;
    const int lane = tid & 31;
    if (lane == 0) {
#pragma unroll
        for (int i = 0; i < 16; i++) sm.red[warp][i] = acc[i];
    }
    __syncthreads();

    // cross-warp reduce in parallel: threads 0..15 each own one statistic
    if (tid < 16) {
        float v = sm.red[0][tid];
#pragma unroll
        for (int w = 1; w < THREADS / 32; w++) v += sm.red[w][tid];
        sm.red[0][tid] = v;
    }
    __syncthreads();

    if (tid != 0) return;

    // ---- thread 0: fast fp32 3x3 SVD + epilogue ----
    float s[16];
#pragma unroll
    for (int i = 0; i < 16; i++) s[i] = sm.red[0][i];

    const float Sw = s[0];
    const float Sx[3] = {s[1], s[2], s[3]};
    const float Tx[3] = {s[4], s[5], s[6]};
    const float M[3][3] = {{s[7], s[8], s[9]},
                           {s[10], s[11], s[12]},
                           {s[13], s[14], s[15]}};

    const float w = Sw + 1e-4f;
    const float winv = __fdividef(1.0f, w);
    float sc[3], tc[3];
#pragma unroll
    for (int i = 0; i < 3; i++) { sc[i] = Sx[i] * winv; tc[i] = Tx[i] * winv; }

    float A[3][3];
#pragma unroll
    for (int i = 0; i < 3; i++)
#pragma unroll
        for (int j = 0; j < 3; j++)
            A[i][j] = (M[i][j] - tc[i] * Sx[j] - Tx[i] * sc[j] + Sw * tc[i] * sc[j]) * winv;

    float Bm[3][3];
#pragma unroll
    for (int i = 0; i < 3; i++)
#pragma unroll
        for (int j = 0; j < 3; j++)
            Bm[i][j] = A[0][i] * A[0][j] + A[1][i] * A[1][j] + A[2][i] * A[2][j];

    float V[3][3] = {{1, 0, 0}, {0, 1, 0}, {0, 0, 1}};

    // cyclic Jacobi, 5 sweeps, fast divides, convergence skip
#pragma unroll 1
    for (int sweep = 0; sweep < 5; sweep++) {
#pragma unroll
        for (int pair = 0; pair < 3; pair++) {
            const int p = (pair == 2) ? 1 : 0;
            const int q = (pair == 0) ? 1 : 2;
            const float apq = Bm[p][q];
            const float app = Bm[p][p], aqq = Bm[q][q];
            if (apq * apq <= 1e-22f * app * aqq + 1e-38f) continue;
            const float tau = __fdividef(aqq - app, 2.0f * apq);
            const float t = __fdividef((tau >= 0.0f) ? 1.0f : -1.0f,
                                       fabsf(tau) + sqrtf(1.0f + tau * tau));
            const float c = rsqrtf(1.0f + t * t);
            const float sn = t * c;
#pragma unroll
            for (int k = 0; k < 3; k++) {
                const float bkp = Bm[k][p], bkq = Bm[k][q];
                Bm[k][p] = c * bkp - sn * bkq;
                Bm[k][q] = sn * bkp + c * bkq;
            }
#pragma unroll
            for (int k = 0; k < 3; k++) {
                const float bpk = Bm[p][k], bqk = Bm[q][k];
                Bm[p][k] = c * bpk - sn * bqk;
                Bm[q][k] = sn * bpk + c * bqk;
            }
#pragma unroll
            for (int k = 0; k < 3; k++) {
                const float vkp = V[k][p], vkq = V[k][q];
                V[k][p] = c * vkp - sn * vkq;
                V[k][q] = sn * vkp + c * vkq;
            }
        }
    }

    float lam[3] = {Bm[0][0], Bm[1][1], Bm[2][2]};
#pragma unroll
    for (int i = 0; i < 2; i++)
#pragma unroll
        for (int j = 0; j < 2 - i; j++)
            if (lam[j] < lam[j + 1]) {
                float tl = lam[j]; lam[j] = lam[j + 1]; lam[j + 1] = tl;
#pragma unroll
                for (int k = 0; k < 3; k++) {
                    float tv = V[k][j]; V[k][j] = V[k][j + 1]; V[k][j + 1] = tv;
                }
            }

    float U[3][3];
    float norms[3];
#pragma unroll
    for (int k = 0; k < 3; k++) {
        float uv[3];
#pragma unroll
        for (int i = 0; i < 3; i++)
            uv[i] = A[i][0] * V[0][k] + A[i][1] * V[1][k] + A[i][2] * V[2][k];
        const float nsq = uv[0] * uv[0] + uv[1] * uv[1] + uv[2] * uv[2];
        norms[k] = sqrtf(nsq);
        const float inv = (nsq > 1e-36f) ? rsqrtf(nsq) : 0.0f;
#pragma unroll
        for (int i = 0; i < 3; i++) U[i][k] = uv[i] * inv;
    }
    if (norms[2] < 1e-7f * (norms[0] + 1e-30f)) {
        U[0][2] = U[1][0] * U[2][1] - U[2][0] * U[1][1];
        U[1][2] = U[2][0] * U[0][1] - U[0][0] * U[2][1];
        U[2][2] = U[0][0] * U[1][1] - U[1][0] * U[0][1];
    }

    const float d = det3f(U) * det3f(V);

    float R[3][3];
#pragma unroll
    for (int i = 0; i < 3; i++)
#pragma unroll
        for (int j = 0; j < 3; j++)
            R[i][j] = U[i][0] * V[j][0] + U[i][1] * V[j][1] + d * U[i][2] * V[j][2];

    float t1[3], t[3];
#pragma unroll
    for (int i = 0; i < 3; i++)
        t1[i] = sc[i] - (R[0][i] * tc[0] + R[1][i] * tc[1] + R[2][i] * tc[2]);
#pragma unroll
    for (int i = 0; i < 3; i++)
        t[i] = -(R[i][0] * t1[0] + R[i][1] * t1[1] + R[i][2] * t1[2]);

    float* Rout = out + (size_t)b * 9;
    float* Tout = out + (size_t)B * 9 + (size_t)b * 3;
#pragma unroll
    for (int i = 0; i < 3; i++)
#pragma unroll
        for (int j = 0; j < 3; j++)
            Rout[i * 3 + j] = R[i][j];
#pragma unroll
    for (int i = 0; i < 3; i++) Tout[i] = t[i];
}

// ---------------------------------------------------------------------------

extern "C" void kernel_launch(void* const* d_in, const int* in_sizes, int n_in,
                              void* d_out, int out_size)
{
    const float* src = (const float*)d_in[0];
    const float* tgt = (const float*)d_in[1];
    const float* wts = (const float*)d_in[2];
    float* out = (float*)d_out;

    const int B = out_size / 12;            // 9 (R) + 3 (t) per batch
    const int N = in_sizes[2] / B;          // weights are (B,1,N)

    kabsch_kernel<<<B, THREADS>>>(src, tgt, wts, out, N, B);
}

// round 14
// speedup vs baseline: 1.1391x; 1.0609x over previous
#include <cuda_runtime.h>
#include <math.h>

// ---------------------------------------------------------------------------
// Weighted Kabsch, two-kernel split.
// Kernel 1: pure streaming reduce (one CTA per batch, direct LDG.128, no
// epilogue tail -> every resident CTA streams 100% of its lifetime).
// Kernel 2: 2048 independent fp32 3x3 SVD chains spread across 64 SMs
// (grid=64 x 32 threads) -> ~2us instead of 10us at grid=16 x 128.
// ---------------------------------------------------------------------------

#define MAX_B 2048
#define RED_THREADS 256

// 16 sufficient statistics per batch:
// [0] sum w | [1:4] sum w*src | [4:7] sum w*tgt | [7:16] sum w*tgt_i*src_j
__device__ float g_sums[MAX_B][16];

__global__ void __launch_bounds__(RED_THREADS)
reduce_kernel(const float* __restrict__ src,
              const float* __restrict__ tgt,
              const float* __restrict__ wts,
              int N)
{
    const int b = blockIdx.x;
    const float4* s4 = (const float4*)(src + (size_t)b * N * 3);
    const float4* t4 = (const float4*)(tgt + (size_t)b * N * 3);
    const float4* w4 = (const float4*)(wts + (size_t)b * N);

    float acc[16];
#pragma unroll
    for (int i = 0; i < 16; i++) acc[i] = 0.f;

    const int tid = threadIdx.x;
    const int ngroups = N >> 2;  // N divisible by 4

    for (int g = tid; g < ngroups; g += RED_THREADS) {
        float4 wv = w4[g];
        float4 a0 = s4[g * 3 + 0];
        float4 a1 = s4[g * 3 + 1];
        float4 a2 = s4[g * 3 + 2];
        float4 b0 = t4[g * 3 + 0];
        float4 b1 = t4[g * 3 + 1];
        float4 b2 = t4[g * 3 + 2];

        const float sx[4][3] = {{a0.x, a0.y, a0.z},
                                {a0.w, a1.x, a1.y},
                                {a1.z, a1.w, a2.x},
                                {a2.y, a2.z, a2.w}};
        const float tx[4][3] = {{b0.x, b0.y, b0.z},
                                {b0.w, b1.x, b1.y},
                                {b1.z, b1.w, b2.x},
                                {b2.y, b2.z, b2.w}};
        const float wa[4] = {wv.x, wv.y, wv.z, wv.w};

#pragma unroll
        for (int p = 0; p < 4; p++) {
            const float w = wa[p];
            const float s0 = sx[p][0], s1 = sx[p][1], s2 = sx[p][2];
            const float wt0 = w * tx[p][0];
            const float wt1 = w * tx[p][1];
            const float wt2 = w * tx[p][2];
            acc[0] += w;
            acc[1] += w * s0;  acc[2] += w * s1;  acc[3] += w * s2;
            acc[4] += wt0;     acc[5] += wt1;     acc[6] += wt2;
            acc[7]  += wt0 * s0;  acc[8]  += wt0 * s1;  acc[9]  += wt0 * s2;
            acc[10] += wt1 * s0;  acc[11] += wt1 * s1;  acc[12] += wt1 * s2;
            acc[13] += wt2 * s0;  acc[14] += wt2 * s1;  acc[15] += wt2 * s2;
        }
    }

    // warp reduce
#pragma unroll
    for (int i = 0; i < 16; i++) {
#pragma unroll
        for (int o = 16; o > 0; o >>= 1)
            acc[i] += __shfl_down_sync(0xffffffffu, acc[i], o);
    }

    __shared__ float smem[RED_THREADS / 32][16];
    const int warp = tid >> 5;
    const int lane = tid & 31;
    if (lane == 0) {
#pragma unroll
        for (int i = 0; i < 16; i++) smem[warp][i] = acc[i];
    }
    __syncthreads();

    if (tid < 16) {
        float v = 0.f;
#pragma unroll
        for (int w = 0; w < RED_THREADS / 32; w++) v += smem[w][tid];
        g_sums[b][tid] = v;
    }
}

// ---------------------------------------------------------------------------

__device__ __forceinline__ float det3f(const float m[3][3]) {
    return m[0][0] * (m[1][1] * m[2][2] - m[1][2] * m[2][1])
         - m[0][1] * (m[1][0] * m[2][2] - m[1][2] * m[2][0])
         + m[0][2] * (m[1][0] * m[2][1] - m[1][1] * m[2][0]);
}

// 32 threads per CTA: one batch per thread, 64 CTAs -> 64 SMs in parallel.
__global__ void __launch_bounds__(32)
svd_kernel(float* __restrict__ out, int B)
{
    const int b = blockIdx.x * 32 + threadIdx.x;
    if (b >= B) return;

    const float* s = g_sums[b];
    const float Sw = s[0];
    const float Sx[3] = {s[1], s[2], s[3]};
    const float Tx[3] = {s[4], s[5], s[6]};
    const float M[3][3] = {{s[7], s[8], s[9]},
                           {s[10], s[11], s[12]},
                           {s[13], s[14], s[15]}};

    const float w = Sw + 1e-4f;
    const float winv = __fdividef(1.0f, w);
    float sc[3], tc[3];
#pragma unroll
    for (int i = 0; i < 3; i++) { sc[i] = Sx[i] * winv; tc[i] = Tx[i] * winv; }

    // A = weighted cross-covariance (tgt rows, src cols), centered
    float A[3][3];
#pragma unroll
    for (int i = 0; i < 3; i++)
#pragma unroll
        for (int j = 0; j < 3; j++)
            A[i][j] = (M[i][j] - tc[i] * Sx[j] - Tx[i] * sc[j] + Sw * tc[i] * sc[j]) * winv;

    // Bm = A^T A (symmetric PSD)
    float Bm[3][3];
#pragma unroll
    for (int i = 0; i < 3; i++)
#pragma unroll
        for (int j = 0; j < 3; j++)
            Bm[i][j] = A[0][i] * A[0][j] + A[1][i] * A[1][j] + A[2][i] * A[2][j];

    float V[3][3] = {{1, 0, 0}, {0, 1, 0}, {0, 0, 1}};

    // cyclic Jacobi, 5 sweeps, fast divides, convergence skip
#pragma unroll 1
    for (int sweep = 0; sweep < 5; sweep++) {
#pragma unroll
        for (int pair = 0; pair < 3; pair++) {
            const int p = (pair == 2) ? 1 : 0;
            const int q = (pair == 0) ? 1 : 2;
            const float apq = Bm[p][q];
            const float app = Bm[p][p], aqq = Bm[q][q];
            if (apq * apq <= 1e-22f * app * aqq + 1e-38f) continue;
            const float tau = __fdividef(aqq - app, 2.0f * apq);
            const float t = __fdividef((tau >= 0.0f) ? 1.0f : -1.0f,
                                       fabsf(tau) + sqrtf(1.0f + tau * tau));
            const float c = rsqrtf(1.0f + t * t);
            const float sn = t * c;
#pragma unroll
            for (int k = 0; k < 3; k++) {
                const float bkp = Bm[k][p], bkq = Bm[k][q];
                Bm[k][p] = c * bkp - sn * bkq;
                Bm[k][q] = sn * bkp + c * bkq;
            }
#pragma unroll
            for (int k = 0; k < 3; k++) {
                const float bpk = Bm[p][k], bqk = Bm[q][k];
                Bm[p][k] = c * bpk - sn * bqk;
                Bm[q][k] = sn * bpk + c * bqk;
            }
#pragma unroll
            for (int k = 0; k < 3; k++) {
                const float vkp = V[k][p], vkq = V[k][q];
                V[k][p] = c * vkp - sn * vkq;
                V[k][q] = sn * vkp + c * vkq;
            }
        }
    }

    float lam[3] = {Bm[0][0], Bm[1][1], Bm[2][2]};
    // sort eigenvalues descending (with V column swaps) to match jnp svd order
#pragma unroll
    for (int i = 0; i < 2; i++)
#pragma unroll
        for (int j = 0; j < 2 - i; j++)
            if (lam[j] < lam[j + 1]) {
                float tl = lam[j]; lam[j] = lam[j + 1]; lam[j + 1] = tl;
#pragma unroll
                for (int k = 0; k < 3; k++) {
                    float tv = V[k][j]; V[k][j] = V[k][j + 1]; V[k][j + 1] = tv;
                }
            }

    // U columns: A v_k / |A v_k|
    float U[3][3];
    float norms[3];
#pragma unroll
    for (int k = 0; k < 3; k++) {
        float uv[3];
#pragma unroll
        for (int i = 0; i < 3; i++)
            uv[i] = A[i][0] * V[0][k] + A[i][1] * V[1][k] + A[i][2] * V[2][k];
        const float nsq = uv[0] * uv[0] + uv[1] * uv[1] + uv[2] * uv[2];
        norms[k] = sqrtf(nsq);
        const float inv = (nsq > 1e-36f) ? rsqrtf(nsq) : 0.0f;
#pragma unroll
        for (int i = 0; i < 3; i++) U[i][k] = uv[i] * inv;
    }
    // degenerate smallest singular value -> complete right-handed frame
    if (norms[2] < 1e-7f * (norms[0] + 1e-30f)) {
        U[0][2] = U[1][0] * U[2][1] - U[2][0] * U[1][1];
        U[1][2] = U[2][0] * U[0][1] - U[0][0] * U[2][1];
        U[2][2] = U[0][0] * U[1][1] - U[1][0] * U[0][1];
    }

    const float d = det3f(U) * det3f(V);

    // R = U diag(1,1,d) V^T
    float R[3][3];
#pragma unroll
    for (int i = 0; i < 3; i++)
#pragma unroll
        for (int j = 0; j < 3; j++)
            R[i][j] = U[i][0] * V[j][0] + U[i][1] * V[j][1] + d * U[i][2] * V[j][2];

    // t1 = src_centroid - R^T tgt_centroid ; t = -R t1
    float t1[3], t[3];
#pragma unroll
    for (int i = 0; i < 3; i++)
        t1[i] = sc[i] - (R[0][i] * tc[0] + R[1][i] * tc[1] + R[2][i] * tc[2]);
#pragma unroll
    for (int i = 0; i < 3; i++)
        t[i] = -(R[i][0] * t1[0] + R[i][1] * t1[1] + R[i][2] * t1[2]);

    // outputs: R flattened (B,3,3) then t flattened (B,3,1)
    float* Rout = out + (size_t)b * 9;
    float* Tout = out + (size_t)B * 9 + (size_t)b * 3;
#pragma unroll
    for (int i = 0; i < 3; i++)
#pragma unroll
        for (int j = 0; j < 3; j++)
            Rout[i * 3 + j] = R[i][j];
#pragma unroll
    for (int i = 0; i < 3; i++) Tout[i] = t[i];
}

// ---------------------------------------------------------------------------

extern "C" void kernel_launch(void* const* d_in, const int* in_sizes, int n_in,
                              void* d_out, int out_size)
{
    const float* src = (const float*)d_in[0];
    const float* tgt = (const float*)d_in[1];
    const float* wts = (const float*)d_in[2];
    float* out = (float*)d_out;

    const int B = out_size / 12;            // 9 (R) + 3 (t) per batch
    const int N = in_sizes[2] / B;          // weights are (B,1,N)

    reduce_kernel<<<B, RED_THREADS>>>(src, tgt, wts, N);
    svd_kernel<<<(B + 31) / 32, 32>>>(out, B);
}